// round 13
// baseline (speedup 1.0000x reference)
#include <cuda_runtime.h>
#include <math.h>

// ---------------- problem constants ----------------
#define B_ 32
#define T_ 512
#define J_ 64
#define E_ 300
#define H_ 256

static constexpr size_t NCs = 16384;  // B*T
static constexpr size_t NQs = 2048;   // B*J

// ---------------- scratch layout (single __device__ arena) ----------------
static constexpr size_t OFF_CX    = 0;                          // [NC][300]
static constexpr size_t OFF_QX    = OFF_CX   + NCs * 300;       // [NQ][300]
static constexpr size_t OFF_HB    = OFF_QX   + NQs * 300;       // [NC][300]
static constexpr size_t OFF_TB    = OFF_HB   + NCs * 300;       // [NC][300]
static constexpr size_t OFF_CREP  = OFF_TB   + NCs * 300;       // [NC][512]
static constexpr size_t OFF_QREP  = OFF_CREP + NCs * 512;       // [NQ][512]
static constexpr size_t OFF_G     = OFF_QREP + NQs * 512;       // [NC][2048]
static constexpr size_t OFF_MA    = OFF_G    + NCs * 2048;      // [NC][512]
static constexpr size_t OFF_MB    = OFF_MA   + NCs * 512;       // [NC][512]
static constexpr size_t OFF_M2    = OFF_MB   + NCs * 512;       // [NC][512]
static constexpr size_t OFF_GATES = OFF_M2   + NCs * 512;       // [NC][2048] (GEMM out, both dirs)
static constexpr size_t OFF_GT    = OFF_GATES + 2 * NCs * 1024; // [2][T][1024][32] transposed
static constexpr size_t OFF_H     = OFF_GT   + 2 * NCs * 1024;  // 2 x [2][256][32]
static constexpr size_t OFF_SMAX  = OFF_H    + 2 * 16384;       // [NC]
static constexpr size_t OFF_UW2   = OFF_SMAX + 16384;           // [NQ]
static constexpr size_t OFF_Q2C   = OFF_UW2  + 2048;            // [B][512]
static constexpr size_t SCRATCH_TOTAL = OFF_Q2C + 32 * 512;

__device__ float g_scratch[SCRATCH_TOTAL];
__device__ unsigned g_barcnt2[2];

__device__ __forceinline__ float sigmoidf_(float x) { return 1.f / (1.f + expf(-x)); }

__device__ __forceinline__ unsigned tf32r_(float x) {
    unsigned u;
    asm("cvt.rna.tf32.f32 %0, %1;" : "=r"(u) : "f"(x));
    return u;
}

__device__ __forceinline__ void mma_tf32_(float* c, const unsigned* a, const unsigned* b) {
    asm volatile(
        "mma.sync.aligned.m16n8k8.row.col.f32.tf32.tf32.f32 "
        "{%0,%1,%2,%3}, {%4,%5,%6,%7}, {%8,%9}, {%0,%1,%2,%3};\n"
        : "+f"(c[0]), "+f"(c[1]), "+f"(c[2]), "+f"(c[3])
        : "r"(a[0]), "r"(a[1]), "r"(a[2]), "r"(a[3]), "r"(b[0]), "r"(b[1]));
}

// ---------------- embedding gather ----------------
__global__ void __launch_bounds__(256) gather_embed(
    const int* __restrict__ tok, const float* __restrict__ emb,
    float* __restrict__ out, int nrows)
{
    int idx = blockIdx.x * 256 + threadIdx.x;
    int total = nrows * E_;
    if (idx >= total) return;
    int r = idx / E_;
    int e = idx - r * E_;
    out[idx] = emb[(size_t)tok[r] * E_ + e];
}

// ---------------- highway combine ----------------
__global__ void __launch_bounds__(256) hw_combine(
    float* __restrict__ x, const float* __restrict__ h,
    const float* __restrict__ t, int n)
{
    int i = blockIdx.x * 256 + threadIdx.x;
    if (i < n) { float tv = t[i]; x[i] = h[i] * tv + (1.f - tv) * x[i]; }
}

// ---------------- TF32 tensor-core GEMM: C[M,N] = A[M,K] @ B[N,K]^T ----------------
// 128x128 block tile, KT=32, 8 warps (2m x 4n), warp tile 64x32 = 4x4 m16n8k8 atoms.
// fp32 in/out, tf32 (cvt.rna) inside. Optional bias1+bias2 and relu.
__global__ void __launch_bounds__(256) mma_tn(
    const float* __restrict__ A, const float* __restrict__ Bm,
    float* __restrict__ C,
    const float* __restrict__ bias1, const float* __restrict__ bias2,
    int M, int N, int K, int relu)
{
    __shared__ unsigned As[128][36];
    __shared__ unsigned Bs[128][36];
    const int tid = threadIdx.x;
    const int warp = tid >> 5, lane = tid & 31;
    const int wm = warp >> 2, wn = warp & 3;      // 2 x 4 warp grid
    const int grp = lane >> 2, tig = lane & 3;
    const int bm = blockIdx.y * 128, bn = blockIdx.x * 128;
    const int lrow = tid >> 3;                    // 0..31 (+p*32)
    const int lc4 = (tid & 7) << 2;               // k offset 0..28

    float c[4][4][4];
#pragma unroll
    for (int i = 0; i < 4; i++)
#pragma unroll
        for (int j = 0; j < 4; j++)
#pragma unroll
            for (int r = 0; r < 4; r++) c[i][j][r] = 0.f;

    unsigned av[4][4], bv[4][4];   // staged tf32 values for the current K-tile

    // ---- prologue: load first K-tile into regs ----
    {
        int k0 = 0;
#pragma unroll
        for (int p = 0; p < 4; p++) {
            int row = lrow + p * 32;
            float4 va = make_float4(0.f, 0.f, 0.f, 0.f);
            float4 vb = make_float4(0.f, 0.f, 0.f, 0.f);
            int ki = k0 + lc4;
            if (bm + row < M) {
                if (ki + 3 < K) va = *(const float4*)(A + (size_t)(bm + row) * K + ki);
                else {
                    float t[4] = {0.f, 0.f, 0.f, 0.f};
                    for (int e = 0; e < 4; e++) if (ki + e < K) t[e] = A[(size_t)(bm + row) * K + ki + e];
                    va = make_float4(t[0], t[1], t[2], t[3]);
                }
            }
            if (bn + row < N) {
                if (ki + 3 < K) vb = *(const float4*)(Bm + (size_t)(bn + row) * K + ki);
                else {
                    float t[4] = {0.f, 0.f, 0.f, 0.f};
                    for (int e = 0; e < 4; e++) if (ki + e < K) t[e] = Bm[(size_t)(bn + row) * K + ki + e];
                    vb = make_float4(t[0], t[1], t[2], t[3]);
                }
            }
            av[p][0] = tf32r_(va.x); av[p][1] = tf32r_(va.y);
            av[p][2] = tf32r_(va.z); av[p][3] = tf32r_(va.w);
            bv[p][0] = tf32r_(vb.x); bv[p][1] = tf32r_(vb.y);
            bv[p][2] = tf32r_(vb.z); bv[p][3] = tf32r_(vb.w);
        }
    }

    const int nkt = (K + 31) / 32;
    for (int kt = 0; kt < nkt; kt++) {
        // store staged tile to smem
#pragma unroll
        for (int p = 0; p < 4; p++) {
            int row = lrow + p * 32;
            As[row][lc4 + 0] = av[p][0]; As[row][lc4 + 1] = av[p][1];
            As[row][lc4 + 2] = av[p][2]; As[row][lc4 + 3] = av[p][3];
            Bs[row][lc4 + 0] = bv[p][0]; Bs[row][lc4 + 1] = bv[p][1];
            Bs[row][lc4 + 2] = bv[p][2]; Bs[row][lc4 + 3] = bv[p][3];
        }
        __syncthreads();

        // prefetch next K-tile
        if (kt + 1 < nkt) {
            int k0 = (kt + 1) * 32;
#pragma unroll
            for (int p = 0; p < 4; p++) {
                int row = lrow + p * 32;
                float4 va = make_float4(0.f, 0.f, 0.f, 0.f);
                float4 vb = make_float4(0.f, 0.f, 0.f, 0.f);
                int ki = k0 + lc4;
                if (bm + row < M) {
                    if (ki + 3 < K) va = *(const float4*)(A + (size_t)(bm + row) * K + ki);
                    else {
                        float t[4] = {0.f, 0.f, 0.f, 0.f};
                        for (int e = 0; e < 4; e++) if (ki + e < K) t[e] = A[(size_t)(bm + row) * K + ki + e];
                        va = make_float4(t[0], t[1], t[2], t[3]);
                    }
                }
                if (bn + row < N) {
                    if (ki + 3 < K) vb = *(const float4*)(Bm + (size_t)(bn + row) * K + ki);
                    else {
                        float t[4] = {0.f, 0.f, 0.f, 0.f};
                        for (int e = 0; e < 4; e++) if (ki + e < K) t[e] = Bm[(size_t)(bn + row) * K + ki + e];
                        vb = make_float4(t[0], t[1], t[2], t[3]);
                    }
                }
                av[p][0] = tf32r_(va.x); av[p][1] = tf32r_(va.y);
                av[p][2] = tf32r_(va.z); av[p][3] = tf32r_(va.w);
                bv[p][0] = tf32r_(vb.x); bv[p][1] = tf32r_(vb.y);
                bv[p][2] = tf32r_(vb.z); bv[p][3] = tf32r_(vb.w);
            }
        }

        // compute: 4 k-steps of 8
#pragma unroll
        for (int ks = 0; ks < 4; ks++) {
            unsigned af[4][4], bf[4][2];
#pragma unroll
            for (int am = 0; am < 4; am++) {
                int row = wm * 64 + am * 16 + grp;
                af[am][0] = As[row][ks * 8 + tig];
                af[am][1] = As[row + 8][ks * 8 + tig];
                af[am][2] = As[row][ks * 8 + tig + 4];
                af[am][3] = As[row + 8][ks * 8 + tig + 4];
            }
#pragma unroll
            for (int an = 0; an < 4; an++) {
                int col = wn * 32 + an * 8 + grp;
                bf[an][0] = Bs[col][ks * 8 + tig];
                bf[an][1] = Bs[col][ks * 8 + tig + 4];
            }
#pragma unroll
            for (int am = 0; am < 4; am++)
#pragma unroll
                for (int an = 0; an < 4; an++)
                    mma_tf32_(c[am][an], af[am], bf[an]);
        }
        __syncthreads();
    }

    // ---- epilogue ----
#pragma unroll
    for (int am = 0; am < 4; am++) {
        int row0 = bm + wm * 64 + am * 16 + grp;
#pragma unroll
        for (int an = 0; an < 4; an++) {
            int col0 = bn + wn * 32 + an * 8 + tig * 2;
#pragma unroll
            for (int half = 0; half < 2; half++) {
                int row = row0 + half * 8;
                if (row >= M) continue;
#pragma unroll
                for (int e = 0; e < 2; e++) {
                    int col = col0 + e;
                    if (col >= N) continue;
                    float v = c[am][an][half * 2 + e];
                    if (bias1) v += bias1[col];
                    if (bias2) v += bias2[col];
                    if (relu) v = fmaxf(v, 0.f);
                    C[(size_t)row * N + col] = v;
                }
            }
        }
    }
}

// ---------------- gate transpose: gates[b*T+t][2048] -> gt[d][t][g][b] ----------------
__global__ void __launch_bounds__(256) tgates_kernel(
    const float* __restrict__ gates, float* __restrict__ gt, int T)
{
    __shared__ float sm[128][33];
    const int tid = threadIdx.x;
    const int gc = blockIdx.x;      // 0..7 (128 g each)
    const int t  = blockIdx.y;
    const int d  = blockIdx.z;
#pragma unroll
    for (int pass = 0; pass < 16; pass++) {
        int b = pass * 2 + (tid >> 7);
        int g = tid & 127;
        sm[g][b] = gates[((size_t)b * T + t) * 2048 + d * 1024 + gc * 128 + g];
    }
    __syncthreads();
    const size_t obase = (((size_t)(d * T + t)) * 1024 + gc * 128) * 32;
#pragma unroll
    for (int pass = 0; pass < 16; pass++) {
        int g = pass * 8 + (tid >> 5);
        int b = tid & 31;
        gt[obase + (size_t)g * 32 + b] = sm[g][b];
    }
}

// ---------------- persistent biLSTM recurrence (v4) ----------------
__global__ void reset_bar() { g_barcnt2[0] = 0u; g_barcnt2[1] = 0u; }

__global__ void __launch_bounds__(256) lstm_persist(
    const float* __restrict__ gt, const float* __restrict__ whh,
    float* __restrict__ hbuf, float* __restrict__ rep, int T)
{
    __shared__ float sh[32 * 260];      // h_prev (this dir), [b][k] padded
    __shared__ float wsm[16 * 256];     // this block's 16 weight rows
    __shared__ float exch[4][4][32];    // [unit][gate][batch] pre-activations

    const int tid  = threadIdx.x;
    const int d    = blockIdx.x >> 6;
    const int ublk = blockIdx.x & 63;
    const int w    = tid >> 5;
    const int lane = tid & 31;
    const int ui   = w >> 1;
    const int gp   = w & 1;
    const int ug   = (ublk << 2) + ui;
    const int bb   = lane;

    for (int g = 0; g < 2; g++) {
        int gate = gp * 2 + g;
        const float4* src = (const float4*)(whh + ((size_t)d * 1024 + gate * 256 + ug) * 256);
        float4* dst = (float4*)(wsm + (ui * 4 + gate) * 256);
        for (int i = lane; i < 64; i += 32) dst[i] = src[i];
    }

    const float4* wp0 = (const float4*)(wsm + (ui * 4 + gp * 2) * 256);
    const float4* wp1 = wp0 + 64;

    const size_t gtd = (size_t)d * T;
    float cc = 0.f;

    int t0 = (d == 0) ? 0 : (T - 1);
    size_t gb0 = ((gtd + t0) * 1024 + (size_t)(gp * 2) * 256 + ug) * 32 + bb;
    float cg0 = gt[gb0];
    float cg1 = gt[gb0 + 256 * 32];

    for (int s = 0; s < T; s++) {
        const float* hprev = hbuf + (size_t)(s & 1) * 16384;
        float* hnext       = hbuf + (size_t)((s & 1) ^ 1) * 16384;

        if (s == 0) {
            for (int idx = tid; idx < 32 * 256; idx += 256) {
                int b = idx & 31, k = idx >> 5;
                sh[b * 260 + k] = 0.f;
            }
        } else {
            for (int idx = tid; idx < 32 * 256; idx += 256) {
                int b = idx & 31, k = idx >> 5;
                sh[b * 260 + k] = hprev[(d * 256 + k) * 32 + b];
            }
        }

        float ng0 = 0.f, ng1 = 0.f;
        if (s + 1 < T) {
            int tn = (d == 0) ? (s + 1) : (T - 2 - s);
            size_t gn = ((gtd + tn) * 1024 + (size_t)(gp * 2) * 256 + ug) * 32 + bb;
            ng0 = gt[gn];
            ng1 = gt[gn + 256 * 32];
        }
        __syncthreads();

        float a0 = 0.f, a1 = 0.f;
        const float4* hv = (const float4*)(sh + bb * 260);
#pragma unroll 8
        for (int k4 = 0; k4 < 64; k4++) {
            float4 wa = wp0[k4], wb = wp1[k4];
            float4 h4 = hv[k4];
            a0 += wa.x * h4.x + wa.y * h4.y + wa.z * h4.z + wa.w * h4.w;
            a1 += wb.x * h4.x + wb.y * h4.y + wb.z * h4.z + wb.w * h4.w;
        }
        exch[ui][gp * 2 + 0][bb] = a0 + cg0;
        exch[ui][gp * 2 + 1][bb] = a1 + cg1;
        cg0 = ng0; cg1 = ng1;
        __syncthreads();

        if (gp == 0) {
            float xi = exch[ui][0][bb];
            float xf = exch[ui][1][bb];
            float xg = exch[ui][2][bb];
            float xo = exch[ui][3][bb];
            float ig = sigmoidf_(xi), fg = sigmoidf_(xf), og = sigmoidf_(xo);
            float gg = tanhf(xg);
            float cn = fg * cc + ig * gg;
            cc = cn;
            float hn = og * tanhf(cn);
            const int t = (d == 0) ? s : (T - 1 - s);
            hnext[(d * 256 + ug) * 32 + bb] = hn;
            rep[((size_t)bb * T + t) * 512 + (d << 8) + ug] = hn;
        }

        __syncthreads();
        if (tid == 0) {
            unsigned* ctr = &g_barcnt2[d];
            asm volatile("red.release.gpu.global.add.u32 [%0], 1;" :: "l"(ctr) : "memory");
            unsigned target = 64u * (unsigned)(s + 1), v;
            do {
                asm volatile("ld.acquire.gpu.global.u32 %0, [%1];" : "=r"(v) : "l"(ctr) : "memory");
            } while (v < target);
        }
        __syncthreads();
    }
}

// ---------------- attention: uw2[r] = dot(U[r], w2) ----------------
__global__ void __launch_bounds__(256) uw2_kernel(
    const float* __restrict__ U, const float* __restrict__ attw, float* __restrict__ uw2)
{
    int w = threadIdx.x >> 5, lane = threadIdx.x & 31;
    int row = blockIdx.x * 8 + w;
    const float* w2 = attw + 512;
    float acc = 0.f;
    const float* u = U + (size_t)row * 512;
    for (int i = lane; i < 512; i += 32) acc += u[i] * w2[i];
#pragma unroll
    for (int o = 16; o; o >>= 1) acc += __shfl_xor_sync(0xffffffffu, acc, o);
    if (lane == 0) uw2[row] = acc;
}

// ---------------- attention main ----------------
__global__ void __launch_bounds__(256) attn_s(
    const float* __restrict__ Hc, const float* __restrict__ U,
    const float* __restrict__ attw, const float* __restrict__ attb,
    const float* __restrict__ uw2, float* __restrict__ G, float* __restrict__ Smax)
{
    __shared__ float hc[512], hw3[512], sS[64], wsum[8];
    __shared__ float sHw1, sMx, sSum;
    const int row = blockIdx.x;
    const int b = row >> 9;
    const int tid = threadIdx.x;
    const float* w1 = attw;
    const float* w3 = attw + 1024;
    float p0 = 0.f;
    for (int i = tid; i < 512; i += 256) {
        float v = Hc[(size_t)row * 512 + i];
        hc[i] = v; hw3[i] = v * w3[i];
        p0 += v * w1[i];
    }
#pragma unroll
    for (int o = 16; o; o >>= 1) p0 += __shfl_xor_sync(0xffffffffu, p0, o);
    int w = tid >> 5, lane = tid & 31;
    if (lane == 0) wsum[w] = p0;
    __syncthreads();
    if (tid == 0) {
        float s = 0.f;
        for (int i = 0; i < 8; i++) s += wsum[i];
        sHw1 = s;
    }
    __syncthreads();
    float bval = attb[0];
    for (int jj = 0; jj < 8; jj++) {
        int j = w * 8 + jj;
        const float* u = U + ((size_t)(b * 64 + j)) * 512;
        float acc = 0.f;
        for (int k = lane; k < 512; k += 32) acc += hw3[k] * u[k];
#pragma unroll
        for (int o = 16; o; o >>= 1) acc += __shfl_xor_sync(0xffffffffu, acc, o);
        if (lane == 0) sS[j] = sHw1 + uw2[b * 64 + j] + acc + bval;
    }
    __syncthreads();
    if (tid == 0) {
        float mx = -1e30f;
        for (int j = 0; j < 64; j++) mx = fmaxf(mx, sS[j]);
        float sm = 0.f;
        for (int j = 0; j < 64; j++) sm += expf(sS[j] - mx);
        sMx = mx; sSum = sm;
        Smax[row] = mx;
    }
    __syncthreads();
    if (tid < 64) sS[tid] = expf(sS[tid] - sMx) / sSum;
    __syncthreads();
    for (int half = 0; half < 2; half++) {
        int dc = tid + half * 256;
        float acc = 0.f;
        for (int j = 0; j < 64; j++)
            acc += sS[j] * U[((size_t)(b * 64 + j)) * 512 + dc];
        float hv = hc[dc];
        G[(size_t)row * 2048 + dc]        = hv;
        G[(size_t)row * 2048 + 512  + dc] = acc;
        G[(size_t)row * 2048 + 1024 + dc] = hv * acc;
    }
}

// ---------------- q2c ----------------
__global__ void __launch_bounds__(256) attn_q2c(
    const float* __restrict__ Smax, const float* __restrict__ Hc, float* __restrict__ q2c)
{
    __shared__ float p[512];
    __shared__ float sMx, sSum;
    const int b = blockIdx.x, tid = threadIdx.x;
    for (int i = tid; i < 512; i += 256) p[i] = Smax[b * 512 + i];
    __syncthreads();
    if (tid == 0) {
        float mx = -1e30f;
        for (int t = 0; t < 512; t++) mx = fmaxf(mx, p[t]);
        float sm = 0.f;
        for (int t = 0; t < 512; t++) sm += expf(p[t] - mx);
        sMx = mx; sSum = sm;
    }
    __syncthreads();
    for (int i = tid; i < 512; i += 256) p[i] = expf(p[i] - sMx) / sSum;
    __syncthreads();
    for (int half = 0; half < 2; half++) {
        int dc = tid + half * 256;
        float acc = 0.f;
        for (int t = 0; t < 512; t++)
            acc += p[t] * Hc[((size_t)(b * 512 + t)) * 512 + dc];
        q2c[b * 512 + dc] = acc;
    }
}

// ---------------- G[:,1536:2048] = Hc * q2c[b] ----------------
__global__ void __launch_bounds__(256) g4_kernel(
    const float* __restrict__ Hc, const float* __restrict__ q2c, float* __restrict__ G)
{
    int idx = blockIdx.x * 256 + threadIdx.x;
    if (idx >= (int)(NCs * 512)) return;
    int row = idx >> 9, dc = idx & 511;
    int b = row >> 9;
    G[(size_t)row * 2048 + 1536 + dc] = Hc[idx] * q2c[(b << 9) + dc];
}

// ---------------- final logits ----------------
__global__ void __launch_bounds__(256) final_dot(
    const float* __restrict__ G, const float* __restrict__ M,
    const float* __restrict__ pw, const float* __restrict__ pb,
    float* __restrict__ out)
{
    int w = threadIdx.x >> 5, lane = threadIdx.x & 31;
    int row = blockIdx.x * 8 + w;
    float acc = 0.f;
    const float* g = G + (size_t)row * 2048;
    for (int i = lane; i < 2048; i += 32) acc += g[i] * pw[i];
    const float* m = M + (size_t)row * 512;
    for (int i = lane; i < 512; i += 32) acc += m[i] * pw[2048 + i];
#pragma unroll
    for (int o = 16; o; o >>= 1) acc += __shfl_xor_sync(0xffffffffu, acc, o);
    if (lane == 0) out[row] = acc + pb[0];
}

// ---------------- host orchestration ----------------
static inline void launch_sgemm(const float* A, const float* Bm, float* C,
                                const float* b1, const float* b2,
                                int M, int N, int K, int relu)
{
    dim3 grid((N + 127) / 128, (M + 127) / 128);
    mma_tn<<<grid, 256>>>(A, Bm, C, b1, b2, M, N, K, relu);
}

extern "C" void kernel_launch(void* const* d_in, const int* in_sizes, int n_in,
                              void* d_out, int out_size)
{
    (void)in_sizes; (void)n_in; (void)out_size;
    const int*   qtok      = (const int*)d_in[0];
    const int*   ctok      = (const int*)d_in[1];
    const float* emb       = (const float*)d_in[2];
    const float* hw_lin_w  = (const float*)d_in[3];
    const float* hw_lin_b  = (const float*)d_in[4];
    const float* hw_gate_w = (const float*)d_in[5];
    const float* hw_gate_b = (const float*)d_in[6];
    const float* ctx_wih   = (const float*)d_in[7];
    const float* ctx_whh   = (const float*)d_in[8];
    const float* ctx_bih   = (const float*)d_in[9];
    const float* ctx_bhh   = (const float*)d_in[10];
    const float* mod1_wih  = (const float*)d_in[11];
    const float* mod1_whh  = (const float*)d_in[12];
    const float* mod1_bih  = (const float*)d_in[13];
    const float* mod1_bhh  = (const float*)d_in[14];
    const float* mod2_wih  = (const float*)d_in[15];
    const float* mod2_whh  = (const float*)d_in[16];
    const float* mod2_bih  = (const float*)d_in[17];
    const float* mod2_bhh  = (const float*)d_in[18];
    const float* dec_wih   = (const float*)d_in[19];
    const float* dec_whh   = (const float*)d_in[20];
    const float* dec_bih   = (const float*)d_in[21];
    const float* dec_bhh   = (const float*)d_in[22];
    const float* att_w     = (const float*)d_in[23];
    const float* att_b     = (const float*)d_in[24];
    const float* p1_w      = (const float*)d_in[25];
    const float* p1_b      = (const float*)d_in[26];
    const float* p2_w      = (const float*)d_in[27];
    const float* p2_b      = (const float*)d_in[28];
    float* out = (float*)d_out;

    float* S = nullptr;
    cudaGetSymbolAddress((void**)&S, g_scratch);
    float* cx    = S + OFF_CX;
    float* qx    = S + OFF_QX;
    float* hb    = S + OFF_HB;
    float* tb    = S + OFF_TB;
    float* crep  = S + OFF_CREP;
    float* qrep  = S + OFF_QREP;
    float* Gb    = S + OFF_G;
    float* Ma    = S + OFF_MA;
    float* Mb    = S + OFF_MB;
    float* M2b   = S + OFF_M2;
    float* gates = S + OFF_GATES;
    float* gtb   = S + OFF_GT;
    float* Hbuf  = S + OFF_H;
    float* smax  = S + OFF_SMAX;
    float* uw2b  = S + OFF_UW2;
    float* q2cb  = S + OFF_Q2C;

    const int NC = (int)NCs;
    const int NQ = (int)NQs;

    // 1. embedding gather
    gather_embed<<<(NC * E_ + 255) / 256, 256>>>(ctok, emb, cx, NC);
    gather_embed<<<(NQ * E_ + 255) / 256, 256>>>(qtok, emb, qx, NQ);

    // 2. highway (2 layers), context then question
    for (int l = 0; l < 2; l++) {
        launch_sgemm(cx, hw_lin_w + (size_t)l * E_ * E_, hb, hw_lin_b + l * E_, nullptr, NC, E_, E_, 1);
        launch_sgemm(cx, hw_gate_w + (size_t)l * E_ * E_, tb, hw_gate_b + l * E_, nullptr, NC, E_, E_, 1);
        hw_combine<<<(NC * E_ + 255) / 256, 256>>>(cx, hb, tb, NC * E_);
    }
    for (int l = 0; l < 2; l++) {
        launch_sgemm(qx, hw_lin_w + (size_t)l * E_ * E_, hb, hw_lin_b + l * E_, nullptr, NQ, E_, E_, 1);
        launch_sgemm(qx, hw_gate_w + (size_t)l * E_ * E_, tb, hw_gate_b + l * E_, nullptr, NQ, E_, E_, 1);
        hw_combine<<<(NQ * E_ + 255) / 256, 256>>>(qx, hb, tb, NQ * E_);
    }

    // one biLSTM = 1 fused gate GEMM (both dirs, N=2048) + transpose + persistent recurrence
    #define RUN_BILSTM(Xin, WIH, WHH, BIH, BHH, KDIM, ROWS, TLEN, REP)                         \
        do {                                                                                   \
            launch_sgemm((Xin), (WIH), gates, (BIH), (BHH), (ROWS), 2048, (KDIM), 0);          \
            tgates_kernel<<<dim3(8, (TLEN), 2), 256>>>(gates, gtb, (TLEN));                    \
            reset_bar<<<1, 1>>>();                                                             \
            lstm_persist<<<128, 256>>>(gtb, (WHH), Hbuf, (REP), (TLEN));                       \
        } while (0)

    // 3. contextual biLSTM
    RUN_BILSTM(cx, ctx_wih, ctx_whh, ctx_bih, ctx_bhh, E_, NC, T_, crep);
    RUN_BILSTM(qx, ctx_wih, ctx_whh, ctx_bih, ctx_bhh, E_, NQ, J_, qrep);

    // 4. attention -> G
    uw2_kernel<<<NQ / 8, 256>>>(qrep, att_w, uw2b);
    attn_s<<<NC, 256>>>(crep, qrep, att_w, att_b, uw2b, Gb, smax);
    attn_q2c<<<B_, 256>>>(smax, crep, q2cb);
    g4_kernel<<<(NC * 512 + 255) / 256, 256>>>(crep, q2cb, Gb);

    // 5. modeling biLSTMs
    RUN_BILSTM(Gb, mod1_wih, mod1_whh, mod1_bih, mod1_bhh, 2048, NC, T_, Ma);
    RUN_BILSTM(Ma, mod2_wih, mod2_whh, mod2_bih, mod2_bhh, 512, NC, T_, Mb);

    // 6. start logits
    final_dot<<<NC / 8, 256>>>(Gb, Mb, p1_w, p1_b, out);

    // 7. decode biLSTM + end logits
    RUN_BILSTM(Mb, dec_wih, dec_whh, dec_bih, dec_bhh, 512, NC, T_, M2b);
    final_dot<<<NC / 8, 256>>>(Gb, M2b, p2_w, p2_b, out + NC);

    #undef RUN_BILSTM
}

// round 14
// speedup vs baseline: 1.5675x; 1.5675x over previous
#include <cuda_runtime.h>
#include <math.h>

// ---------------- problem constants ----------------
#define B_ 32
#define T_ 512
#define J_ 64
#define E_ 300
#define H_ 256

static constexpr size_t NCs = 16384;  // B*T
static constexpr size_t NQs = 2048;   // B*J

// ---------------- scratch layout (single __device__ arena) ----------------
static constexpr size_t OFF_CX    = 0;                          // [NC][300]
static constexpr size_t OFF_QX    = OFF_CX   + NCs * 300;       // [NQ][300]
static constexpr size_t OFF_HB    = OFF_QX   + NQs * 300;       // [NC][300]
static constexpr size_t OFF_TB    = OFF_HB   + NCs * 300;       // [NC][300]
static constexpr size_t OFF_CREP  = OFF_TB   + NCs * 300;       // [NC][512]
static constexpr size_t OFF_QREP  = OFF_CREP + NCs * 512;       // [NQ][512]
static constexpr size_t OFF_G     = OFF_QREP + NQs * 512;       // [NC][2048]
static constexpr size_t OFF_MA    = OFF_G    + NCs * 2048;      // [NC][512]
static constexpr size_t OFF_MB    = OFF_MA   + NCs * 512;       // [NC][512]
static constexpr size_t OFF_M2    = OFF_MB   + NCs * 512;       // [NC][512]
static constexpr size_t OFF_GATES = OFF_M2   + NCs * 512;       // [NC][2048] (GEMM out, both dirs)
static constexpr size_t OFF_GT    = OFF_GATES + 2 * NCs * 1024; // [2][T][1024][32] transposed
static constexpr size_t OFF_H     = OFF_GT   + 2 * NCs * 1024;  // 2 x [2][256][32]
static constexpr size_t OFF_SMAX  = OFF_H    + 2 * 16384;       // [NC]
static constexpr size_t OFF_UW2   = OFF_SMAX + 16384;           // [NQ]
static constexpr size_t OFF_Q2C   = OFF_UW2  + 2048;            // [B][512]
static constexpr size_t SCRATCH_TOTAL = OFF_Q2C + 32 * 512;

__device__ float g_scratch[SCRATCH_TOTAL];
__device__ unsigned g_barcnt2[2];

__device__ __forceinline__ float sigmoidf_(float x) { return 1.f / (1.f + expf(-x)); }

__device__ __forceinline__ void mma_tf32_(float* c, const unsigned* a, const unsigned* b) {
    asm volatile(
        "mma.sync.aligned.m16n8k8.row.col.f32.tf32.tf32.f32 "
        "{%0,%1,%2,%3}, {%4,%5,%6,%7}, {%8,%9}, {%0,%1,%2,%3};\n"
        : "+f"(c[0]), "+f"(c[1]), "+f"(c[2]), "+f"(c[3])
        : "r"(a[0]), "r"(a[1]), "r"(a[2]), "r"(a[3]), "r"(b[0]), "r"(b[1]));
}

__device__ __forceinline__ void cpa16_(unsigned smem, const void* g, int srcsz) {
    asm volatile("cp.async.ca.shared.global [%0], [%1], 16, %2;"
                 :: "r"(smem), "l"(g), "r"(srcsz));
}
__device__ __forceinline__ void cpa_commit_() {
    asm volatile("cp.async.commit_group;");
}
template <int N>
__device__ __forceinline__ void cpa_wait_() {
    asm volatile("cp.async.wait_group %0;" :: "n"(N));
}

// ---------------- embedding gather ----------------
__global__ void __launch_bounds__(256) gather_embed(
    const int* __restrict__ tok, const float* __restrict__ emb,
    float* __restrict__ out, int nrows)
{
    int idx = blockIdx.x * 256 + threadIdx.x;
    int total = nrows * E_;
    if (idx >= total) return;
    int r = idx / E_;
    int e = idx - r * E_;
    out[idx] = emb[(size_t)tok[r] * E_ + e];
}

// ---------------- highway combine ----------------
__global__ void __launch_bounds__(256) hw_combine(
    float* __restrict__ x, const float* __restrict__ h,
    const float* __restrict__ t, int n)
{
    int i = blockIdx.x * 256 + threadIdx.x;
    if (i < n) { float tv = t[i]; x[i] = h[i] * tv + (1.f - tv) * x[i]; }
}

// ---------------- TF32 tensor-core GEMM v2: C[M,N] = A[M,K] @ B[N,K]^T --------------
// 128x128 tile, KT=16, cp.async double-buffered smem (no cvt: raw fp32 bits ->
// tf32 truncation). 8 warps (2m x 4n), warp tile 64x32 = 4x4 m16n8k8 atoms.
__global__ void __launch_bounds__(256) mma_tn(
    const float* __restrict__ A, const float* __restrict__ Bm,
    float* __restrict__ C,
    const float* __restrict__ bias1, const float* __restrict__ bias2,
    int M, int N, int K, int relu)
{
    __shared__ float As[2][128][20];
    __shared__ float Bs[2][128][20];
    const int tid = threadIdx.x;
    const int warp = tid >> 5, lane = tid & 31;
    const int wm = warp >> 2, wn = warp & 3;      // 2 x 4 warp grid
    const int grp = lane >> 2, tig = lane & 3;
    const int bm = blockIdx.y * 128, bn = blockIdx.x * 128;
    const int cr = tid >> 2;                      // 0..63  (+64)
    const int ck = (tid & 3) << 2;                // 0,4,8,12

    const unsigned sAu = (unsigned)__cvta_generic_to_shared(&As[0][0][0]);
    const unsigned sBu = (unsigned)__cvta_generic_to_shared(&Bs[0][0][0]);

    float c[4][4][4];
#pragma unroll
    for (int i = 0; i < 4; i++)
#pragma unroll
        for (int j = 0; j < 4; j++)
#pragma unroll
            for (int r = 0; r < 4; r++) c[i][j][r] = 0.f;

    const int nkt = (K + 15) / 16;

    // async load of one K-tile stage
    auto issue_stage = [&](int kt, int stage) {
        int k0 = kt * 16;
#pragma unroll
        for (int i = 0; i < 2; i++) {
            int row = cr + i * 64;
            int ki = k0 + ck;
            bool va = (bm + row < M) && (ki < K);
            bool vb = (bn + row < N) && (ki < K);
            const float* ga = A  + (va ? ((size_t)(bm + row) * K + ki) : 0);
            const float* gb = Bm + (vb ? ((size_t)(bn + row) * K + ki) : 0);
            unsigned da = sAu + (unsigned)(((stage * 128 + row) * 20 + ck) * 4);
            unsigned db = sBu + (unsigned)(((stage * 128 + row) * 20 + ck) * 4);
            cpa16_(da, ga, va ? 16 : 0);
            cpa16_(db, gb, vb ? 16 : 0);
        }
        cpa_commit_();
    };

    // prologue: stages 0 and 1 in flight
    issue_stage(0, 0);
    if (nkt > 1) issue_stage(1, 1);

    for (int kt = 0; kt < nkt; kt++) {
        if (kt + 1 < nkt) cpa_wait_<1>(); else cpa_wait_<0>();
        __syncthreads();
        const int st = kt & 1;

        // compute: 2 k-steps of 8
#pragma unroll
        for (int ks = 0; ks < 2; ks++) {
            unsigned af[4][4], bf[4][2];
#pragma unroll
            for (int am = 0; am < 4; am++) {
                int row = wm * 64 + am * 16 + grp;
                af[am][0] = *(const unsigned*)&As[st][row][ks * 8 + tig];
                af[am][1] = *(const unsigned*)&As[st][row + 8][ks * 8 + tig];
                af[am][2] = *(const unsigned*)&As[st][row][ks * 8 + tig + 4];
                af[am][3] = *(const unsigned*)&As[st][row + 8][ks * 8 + tig + 4];
            }
#pragma unroll
            for (int an = 0; an < 4; an++) {
                int col = wn * 32 + an * 8 + grp;
                bf[an][0] = *(const unsigned*)&Bs[st][col][ks * 8 + tig];
                bf[an][1] = *(const unsigned*)&Bs[st][col][ks * 8 + tig + 4];
            }
#pragma unroll
            for (int am = 0; am < 4; am++)
#pragma unroll
                for (int an = 0; an < 4; an++)
                    mma_tf32_(c[am][an], af[am], bf[an]);
        }
        __syncthreads();
        if (kt + 2 < nkt) issue_stage(kt + 2, st);
    }

    // ---- epilogue ----
#pragma unroll
    for (int am = 0; am < 4; am++) {
        int row0 = bm + wm * 64 + am * 16 + grp;
#pragma unroll
        for (int an = 0; an < 4; an++) {
            int col0 = bn + wn * 32 + an * 8 + tig * 2;
#pragma unroll
            for (int half = 0; half < 2; half++) {
                int row = row0 + half * 8;
                if (row >= M) continue;
#pragma unroll
                for (int e = 0; e < 2; e++) {
                    int col = col0 + e;
                    if (col >= N) continue;
                    float v = c[am][an][half * 2 + e];
                    if (bias1) v += bias1[col];
                    if (bias2) v += bias2[col];
                    if (relu) v = fmaxf(v, 0.f);
                    C[(size_t)row * N + col] = v;
                }
            }
        }
    }
}

// ---------------- gate transpose: gates[b*T+t][2048] -> gt[d][t][g][b] ----------------
__global__ void __launch_bounds__(256) tgates_kernel(
    const float* __restrict__ gates, float* __restrict__ gt, int T)
{
    __shared__ float sm[128][33];
    const int tid = threadIdx.x;
    const int gc = blockIdx.x;      // 0..7 (128 g each)
    const int t  = blockIdx.y;
    const int d  = blockIdx.z;
#pragma unroll
    for (int pass = 0; pass < 16; pass++) {
        int b = pass * 2 + (tid >> 7);
        int g = tid & 127;
        sm[g][b] = gates[((size_t)b * T + t) * 2048 + d * 1024 + gc * 128 + g];
    }
    __syncthreads();
    const size_t obase = (((size_t)(d * T + t)) * 1024 + gc * 128) * 32;
#pragma unroll
    for (int pass = 0; pass < 16; pass++) {
        int g = pass * 8 + (tid >> 5);
        int b = tid & 31;
        gt[obase + (size_t)g * 32 + b] = sm[g][b];
    }
}

// ---------------- persistent biLSTM recurrence (v4) ----------------
__global__ void reset_bar() { g_barcnt2[0] = 0u; g_barcnt2[1] = 0u; }

__global__ void __launch_bounds__(256) lstm_persist(
    const float* __restrict__ gt, const float* __restrict__ whh,
    float* __restrict__ hbuf, float* __restrict__ rep, int T)
{
    __shared__ float sh[32 * 260];      // h_prev (this dir), [b][k] padded
    __shared__ float wsm[16 * 256];     // this block's 16 weight rows
    __shared__ float exch[4][4][32];    // [unit][gate][batch] pre-activations

    const int tid  = threadIdx.x;
    const int d    = blockIdx.x >> 6;
    const int ublk = blockIdx.x & 63;
    const int w    = tid >> 5;
    const int lane = tid & 31;
    const int ui   = w >> 1;
    const int gp   = w & 1;
    const int ug   = (ublk << 2) + ui;
    const int bb   = lane;

    for (int g = 0; g < 2; g++) {
        int gate = gp * 2 + g;
        const float4* src = (const float4*)(whh + ((size_t)d * 1024 + gate * 256 + ug) * 256);
        float4* dst = (float4*)(wsm + (ui * 4 + gate) * 256);
        for (int i = lane; i < 64; i += 32) dst[i] = src[i];
    }

    const float4* wp0 = (const float4*)(wsm + (ui * 4 + gp * 2) * 256);
    const float4* wp1 = wp0 + 64;

    const size_t gtd = (size_t)d * T;
    float cc = 0.f;

    int t0 = (d == 0) ? 0 : (T - 1);
    size_t gb0 = ((gtd + t0) * 1024 + (size_t)(gp * 2) * 256 + ug) * 32 + bb;
    float cg0 = gt[gb0];
    float cg1 = gt[gb0 + 256 * 32];

    for (int s = 0; s < T; s++) {
        const float* hprev = hbuf + (size_t)(s & 1) * 16384;
        float* hnext       = hbuf + (size_t)((s & 1) ^ 1) * 16384;

        if (s == 0) {
            for (int idx = tid; idx < 32 * 256; idx += 256) {
                int b = idx & 31, k = idx >> 5;
                sh[b * 260 + k] = 0.f;
            }
        } else {
            for (int idx = tid; idx < 32 * 256; idx += 256) {
                int b = idx & 31, k = idx >> 5;
                sh[b * 260 + k] = hprev[(d * 256 + k) * 32 + b];
            }
        }

        float ng0 = 0.f, ng1 = 0.f;
        if (s + 1 < T) {
            int tn = (d == 0) ? (s + 1) : (T - 2 - s);
            size_t gn = ((gtd + tn) * 1024 + (size_t)(gp * 2) * 256 + ug) * 32 + bb;
            ng0 = gt[gn];
            ng1 = gt[gn + 256 * 32];
        }
        __syncthreads();

        float a0 = 0.f, a1 = 0.f;
        const float4* hv = (const float4*)(sh + bb * 260);
#pragma unroll 8
        for (int k4 = 0; k4 < 64; k4++) {
            float4 wa = wp0[k4], wb = wp1[k4];
            float4 h4 = hv[k4];
            a0 += wa.x * h4.x + wa.y * h4.y + wa.z * h4.z + wa.w * h4.w;
            a1 += wb.x * h4.x + wb.y * h4.y + wb.z * h4.z + wb.w * h4.w;
        }
        exch[ui][gp * 2 + 0][bb] = a0 + cg0;
        exch[ui][gp * 2 + 1][bb] = a1 + cg1;
        cg0 = ng0; cg1 = ng1;
        __syncthreads();

        if (gp == 0) {
            float xi = exch[ui][0][bb];
            float xf = exch[ui][1][bb];
            float xg = exch[ui][2][bb];
            float xo = exch[ui][3][bb];
            float ig = sigmoidf_(xi), fg = sigmoidf_(xf), og = sigmoidf_(xo);
            float gg = tanhf(xg);
            float cn = fg * cc + ig * gg;
            cc = cn;
            float hn = og * tanhf(cn);
            const int t = (d == 0) ? s : (T - 1 - s);
            hnext[(d * 256 + ug) * 32 + bb] = hn;
            rep[((size_t)bb * T + t) * 512 + (d << 8) + ug] = hn;
        }

        __syncthreads();
        if (tid == 0) {
            unsigned* ctr = &g_barcnt2[d];
            asm volatile("red.release.gpu.global.add.u32 [%0], 1;" :: "l"(ctr) : "memory");
            unsigned target = 64u * (unsigned)(s + 1), v;
            do {
                asm volatile("ld.acquire.gpu.global.u32 %0, [%1];" : "=r"(v) : "l"(ctr) : "memory");
            } while (v < target);
        }
        __syncthreads();
    }
}

// ---------------- attention: uw2[r] = dot(U[r], w2) ----------------
__global__ void __launch_bounds__(256) uw2_kernel(
    const float* __restrict__ U, const float* __restrict__ attw, float* __restrict__ uw2)
{
    int w = threadIdx.x >> 5, lane = threadIdx.x & 31;
    int row = blockIdx.x * 8 + w;
    const float* w2 = attw + 512;
    float acc = 0.f;
    const float* u = U + (size_t)row * 512;
    for (int i = lane; i < 512; i += 32) acc += u[i] * w2[i];
#pragma unroll
    for (int o = 16; o; o >>= 1) acc += __shfl_xor_sync(0xffffffffu, acc, o);
    if (lane == 0) uw2[row] = acc;
}

// ---------------- attention main ----------------
__global__ void __launch_bounds__(256) attn_s(
    const float* __restrict__ Hc, const float* __restrict__ U,
    const float* __restrict__ attw, const float* __restrict__ attb,
    const float* __restrict__ uw2, float* __restrict__ G, float* __restrict__ Smax)
{
    __shared__ float hc[512], hw3[512], sS[64], wsum[8];
    __shared__ float sHw1, sMx, sSum;
    const int row = blockIdx.x;
    const int b = row >> 9;
    const int tid = threadIdx.x;
    const float* w1 = attw;
    const float* w3 = attw + 1024;
    float p0 = 0.f;
    for (int i = tid; i < 512; i += 256) {
        float v = Hc[(size_t)row * 512 + i];
        hc[i] = v; hw3[i] = v * w3[i];
        p0 += v * w1[i];
    }
#pragma unroll
    for (int o = 16; o; o >>= 1) p0 += __shfl_xor_sync(0xffffffffu, p0, o);
    int w = tid >> 5, lane = tid & 31;
    if (lane == 0) wsum[w] = p0;
    __syncthreads();
    if (tid == 0) {
        float s = 0.f;
        for (int i = 0; i < 8; i++) s += wsum[i];
        sHw1 = s;
    }
    __syncthreads();
    float bval = attb[0];
    for (int jj = 0; jj < 8; jj++) {
        int j = w * 8 + jj;
        const float* u = U + ((size_t)(b * 64 + j)) * 512;
        float acc = 0.f;
        for (int k = lane; k < 512; k += 32) acc += hw3[k] * u[k];
#pragma unroll
        for (int o = 16; o; o >>= 1) acc += __shfl_xor_sync(0xffffffffu, acc, o);
        if (lane == 0) sS[j] = sHw1 + uw2[b * 64 + j] + acc + bval;
    }
    __syncthreads();
    if (tid == 0) {
        float mx = -1e30f;
        for (int j = 0; j < 64; j++) mx = fmaxf(mx, sS[j]);
        float sm = 0.f;
        for (int j = 0; j < 64; j++) sm += expf(sS[j] - mx);
        sMx = mx; sSum = sm;
        Smax[row] = mx;
    }
    __syncthreads();
    if (tid < 64) sS[tid] = expf(sS[tid] - sMx) / sSum;
    __syncthreads();
    for (int half = 0; half < 2; half++) {
        int dc = tid + half * 256;
        float acc = 0.f;
        for (int j = 0; j < 64; j++)
            acc += sS[j] * U[((size_t)(b * 64 + j)) * 512 + dc];
        float hv = hc[dc];
        G[(size_t)row * 2048 + dc]        = hv;
        G[(size_t)row * 2048 + 512  + dc] = acc;
        G[(size_t)row * 2048 + 1024 + dc] = hv * acc;
    }
}

// ---------------- q2c ----------------
__global__ void __launch_bounds__(256) attn_q2c(
    const float* __restrict__ Smax, const float* __restrict__ Hc, float* __restrict__ q2c)
{
    __shared__ float p[512];
    __shared__ float sMx, sSum;
    const int b = blockIdx.x, tid = threadIdx.x;
    for (int i = tid; i < 512; i += 256) p[i] = Smax[b * 512 + i];
    __syncthreads();
    if (tid == 0) {
        float mx = -1e30f;
        for (int t = 0; t < 512; t++) mx = fmaxf(mx, p[t]);
        float sm = 0.f;
        for (int t = 0; t < 512; t++) sm += expf(p[t] - mx);
        sMx = mx; sSum = sm;
    }
    __syncthreads();
    for (int i = tid; i < 512; i += 256) p[i] = expf(p[i] - sMx) / sSum;
    __syncthreads();
    for (int half = 0; half < 2; half++) {
        int dc = tid + half * 256;
        float acc = 0.f;
        for (int t = 0; t < 512; t++)
            acc += p[t] * Hc[((size_t)(b * 512 + t)) * 512 + dc];
        q2c[b * 512 + dc] = acc;
    }
}

// ---------------- G[:,1536:2048] = Hc * q2c[b] ----------------
__global__ void __launch_bounds__(256) g4_kernel(
    const float* __restrict__ Hc, const float* __restrict__ q2c, float* __restrict__ G)
{
    int idx = blockIdx.x * 256 + threadIdx.x;
    if (idx >= (int)(NCs * 512)) return;
    int row = idx >> 9, dc = idx & 511;
    int b = row >> 9;
    G[(size_t)row * 2048 + 1536 + dc] = Hc[idx] * q2c[(b << 9) + dc];
}

// ---------------- final logits ----------------
__global__ void __launch_bounds__(256) final_dot(
    const float* __restrict__ G, const float* __restrict__ M,
    const float* __restrict__ pw, const float* __restrict__ pb,
    float* __restrict__ out)
{
    int w = threadIdx.x >> 5, lane = threadIdx.x & 31;
    int row = blockIdx.x * 8 + w;
    float acc = 0.f;
    const float* g = G + (size_t)row * 2048;
    for (int i = lane; i < 2048; i += 32) acc += g[i] * pw[i];
    const float* m = M + (size_t)row * 512;
    for (int i = lane; i < 512; i += 32) acc += m[i] * pw[2048 + i];
#pragma unroll
    for (int o = 16; o; o >>= 1) acc += __shfl_xor_sync(0xffffffffu, acc, o);
    if (lane == 0) out[row] = acc + pb[0];
}

// ---------------- host orchestration ----------------
static inline void launch_sgemm(const float* A, const float* Bm, float* C,
                                const float* b1, const float* b2,
                                int M, int N, int K, int relu)
{
    dim3 grid((N + 127) / 128, (M + 127) / 128);
    mma_tn<<<grid, 256>>>(A, Bm, C, b1, b2, M, N, K, relu);
}

extern "C" void kernel_launch(void* const* d_in, const int* in_sizes, int n_in,
                              void* d_out, int out_size)
{
    (void)in_sizes; (void)n_in; (void)out_size;
    const int*   qtok      = (const int*)d_in[0];
    const int*   ctok      = (const int*)d_in[1];
    const float* emb       = (const float*)d_in[2];
    const float* hw_lin_w  = (const float*)d_in[3];
    const float* hw_lin_b  = (const float*)d_in[4];
    const float* hw_gate_w = (const float*)d_in[5];
    const float* hw_gate_b = (const float*)d_in[6];
    const float* ctx_wih   = (const float*)d_in[7];
    const float* ctx_whh   = (const float*)d_in[8];
    const float* ctx_bih   = (const float*)d_in[9];
    const float* ctx_bhh   = (const float*)d_in[10];
    const float* mod1_wih  = (const float*)d_in[11];
    const float* mod1_whh  = (const float*)d_in[12];
    const float* mod1_bih  = (const float*)d_in[13];
    const float* mod1_bhh  = (const float*)d_in[14];
    const float* mod2_wih  = (const float*)d_in[15];
    const float* mod2_whh  = (const float*)d_in[16];
    const float* mod2_bih  = (const float*)d_in[17];
    const float* mod2_bhh  = (const float*)d_in[18];
    const float* dec_wih   = (const float*)d_in[19];
    const float* dec_whh   = (const float*)d_in[20];
    const float* dec_bih   = (const float*)d_in[21];
    const float* dec_bhh   = (const float*)d_in[22];
    const float* att_w     = (const float*)d_in[23];
    const float* att_b     = (const float*)d_in[24];
    const float* p1_w      = (const float*)d_in[25];
    const float* p1_b      = (const float*)d_in[26];
    const float* p2_w      = (const float*)d_in[27];
    const float* p2_b      = (const float*)d_in[28];
    float* out = (float*)d_out;

    float* S = nullptr;
    cudaGetSymbolAddress((void**)&S, g_scratch);
    float* cx    = S + OFF_CX;
    float* qx    = S + OFF_QX;
    float* hb    = S + OFF_HB;
    float* tb    = S + OFF_TB;
    float* crep  = S + OFF_CREP;
    float* qrep  = S + OFF_QREP;
    float* Gb    = S + OFF_G;
    float* Ma    = S + OFF_MA;
    float* Mb    = S + OFF_MB;
    float* M2b   = S + OFF_M2;
    float* gates = S + OFF_GATES;
    float* gtb   = S + OFF_GT;
    float* Hbuf  = S + OFF_H;
    float* smax  = S + OFF_SMAX;
    float* uw2b  = S + OFF_UW2;
    float* q2cb  = S + OFF_Q2C;

    const int NC = (int)NCs;
    const int NQ = (int)NQs;

    // 1. embedding gather
    gather_embed<<<(NC * E_ + 255) / 256, 256>>>(ctok, emb, cx, NC);
    gather_embed<<<(NQ * E_ + 255) / 256, 256>>>(qtok, emb, qx, NQ);

    // 2. highway (2 layers), context then question
    for (int l = 0; l < 2; l++) {
        launch_sgemm(cx, hw_lin_w + (size_t)l * E_ * E_, hb, hw_lin_b + l * E_, nullptr, NC, E_, E_, 1);
        launch_sgemm(cx, hw_gate_w + (size_t)l * E_ * E_, tb, hw_gate_b + l * E_, nullptr, NC, E_, E_, 1);
        hw_combine<<<(NC * E_ + 255) / 256, 256>>>(cx, hb, tb, NC * E_);
    }
    for (int l = 0; l < 2; l++) {
        launch_sgemm(qx, hw_lin_w + (size_t)l * E_ * E_, hb, hw_lin_b + l * E_, nullptr, NQ, E_, E_, 1);
        launch_sgemm(qx, hw_gate_w + (size_t)l * E_ * E_, tb, hw_gate_b + l * E_, nullptr, NQ, E_, E_, 1);
        hw_combine<<<(NQ * E_ + 255) / 256, 256>>>(qx, hb, tb, NQ * E_);
    }

    // one biLSTM = 1 fused gate GEMM (both dirs, N=2048) + transpose + persistent recurrence
    #define RUN_BILSTM(Xin, WIH, WHH, BIH, BHH, KDIM, ROWS, TLEN, REP)                         \
        do {                                                                                   \
            launch_sgemm((Xin), (WIH), gates, (BIH), (BHH), (ROWS), 2048, (KDIM), 0);          \
            tgates_kernel<<<dim3(8, (TLEN), 2), 256>>>(gates, gtb, (TLEN));                    \
            reset_bar<<<1, 1>>>();                                                             \
            lstm_persist<<<128, 256>>>(gtb, (WHH), Hbuf, (REP), (TLEN));                       \
        } while (0)

    // 3. contextual biLSTM
    RUN_BILSTM(cx, ctx_wih, ctx_whh, ctx_bih, ctx_bhh, E_, NC, T_, crep);
    RUN_BILSTM(qx, ctx_wih, ctx_whh, ctx_bih, ctx_bhh, E_, NQ, J_, qrep);

    // 4. attention -> G
    uw2_kernel<<<NQ / 8, 256>>>(qrep, att_w, uw2b);
    attn_s<<<NC, 256>>>(crep, qrep, att_w, att_b, uw2b, Gb, smax);
    attn_q2c<<<B_, 256>>>(smax, crep, q2cb);
    g4_kernel<<<(NC * 512 + 255) / 256, 256>>>(crep, q2cb, Gb);

    // 5. modeling biLSTMs
    RUN_BILSTM(Gb, mod1_wih, mod1_whh, mod1_bih, mod1_bhh, 2048, NC, T_, Ma);
    RUN_BILSTM(Ma, mod2_wih, mod2_whh, mod2_bih, mod2_bhh, 512, NC, T_, Mb);

    // 6. start logits
    final_dot<<<NC / 8, 256>>>(Gb, Mb, p1_w, p1_b, out);

    // 7. decode biLSTM + end logits
    RUN_BILSTM(Mb, dec_wih, dec_whh, dec_bih, dec_bhh, 512, NC, T_, M2b);
    final_dot<<<NC / 8, 256>>>(Gb, M2b, p2_w, p2_b, out + NC);

    #undef RUN_BILSTM
}